// round 4
// baseline (speedup 1.0000x reference)
#include <cuda_runtime.h>
#include <math.h>
#include <stdint.h>

#define Bn 2
#define Nn 512
#define Dn 64
#define EPSf 1e-8f

#define EST_OFF  ((size_t)0)
#define OUT_OFF  ((size_t)131072)
#define QIJ_OFF  ((size_t)262144)
#define Z_OFF    ((size_t)1310720)
#define LH_OFF   ((size_t)68419584)

// ---- device scratch ----
__device__ __align__(16) float g_t[Nn];
__device__ __align__(16) float g_efr[Nn*Dn];
__device__ __align__(16) float g_efi[Nn*Dn];
__device__ __align__(16) float g_Uq[Bn*Nn*128];      // [row][e]  e<64 real, e>=64 imag
__device__ __align__(16) float g_UkT[Bn*128*Nn];     // [b][e][j]
__device__ __align__(16) float g_Uv[Bn*Nn*128];      // [row][e]
__device__ __align__(16) float g_V [Bn*Nn*128];      // [row][e]
__device__ __align__(16) float g_e [Bn*Nn*128];      // er | ei combined
__device__ float g_nq[Bn*Nn];
__device__ float g_nk[Bn*Nn];

__device__ __forceinline__ uint32_t smem_u32(const void* p) {
    uint32_t a;
    asm("{ .reg .u64 t; cvta.to.shared.u64 t, %1; cvt.u32.u64 %0, t; }"
        : "=r"(a) : "l"(p));
    return a;
}

// ============================================================
// K0: t, e^{i phi} tables, lambda_h output
// ============================================================
__global__ void k_setup(const float* __restrict__ tm,
                        const float* __restrict__ lv,
                        float* __restrict__ out_lh)
{
    int idx = blockIdx.x * blockDim.x + threadIdx.x;   // 0..32767
    int i = idx >> 6;
    int d = idx & 63;
    float denom = tm[Nn - 1] - tm[0];
    float ti = tm[i] / denom;
    float lam = (d < 32) ? lv[d] : -lv[d - 32];
    float sph, cph;
    sincosf(ti * lam, &sph, &cph);
    g_efr[idx] = cph;
    g_efi[idx] = sph;
    if (d == 0) g_t[i] = ti;
    if (idx < 128) {
        float v;
        if (idx < 64) v = 0.f;
        else {
            int k = idx - 64;
            v = (k < 32) ? lv[k] : -lv[k - 32];
        }
        out_lh[idx] = v;
    }
}

// ============================================================
// K1: complex projections + twist, all three matrices in one launch.
// grid (128, 3) ; block 256 ; 8 rows per block (4 concurrent x 2 iters)
// ============================================================
__global__ void __launch_bounds__(256) k_proj(
    const float* __restrict__ Zq, const float* __restrict__ Zk,
    const float* __restrict__ Zv,
    const float* __restrict__ Wq, const float* __restrict__ bq,
    const float* __restrict__ Wk, const float* __restrict__ bk,
    const float* __restrict__ Wv, const float* __restrict__ bv)
{
    int m   = blockIdx.y;          // 0=q 1=k 2=v
    int tid = threadIdx.x;
    int d   = tid & 63;
    int sub = tid >> 6;

    const float* Z  = (m == 0) ? Zq : (m == 1) ? Zk : Zv;
    const float* W  = (m == 0) ? Wq : (m == 1) ? Wk : Wv;
    const float* bb = (m == 0) ? bq : (m == 1) ? bk : bv;

    __shared__ float sW0[64 * 65];
    __shared__ float sW1[64 * 65];
    __shared__ float zbuf[4][2][64];
    __shared__ float part[8];

    for (int idx = tid; idx < 4096; idx += 256) {
        int r = idx >> 6, c = idx & 63;
        sW0[r * 65 + c] = W[idx];
        sW1[r * 65 + c] = W[4096 + idx];
    }
    float bR = bb[d], bI = bb[64 + d];
    __syncthreads();

#pragma unroll
    for (int it = 0; it < 2; it++) {
        int row = blockIdx.x * 8 + it * 4 + sub;     // 0..1023
        int b = row >> 9, i = row & 511;

        zbuf[sub][0][d] = Z[((size_t)(b * 2 + 0) * Nn + i) * Dn + d];
        zbuf[sub][1][d] = Z[((size_t)(b * 2 + 1) * Nn + i) * Dn + d];
        __syncthreads();

        float yr = bR, yi = bI;
#pragma unroll 16
        for (int e = 0; e < 64; e++) {
            float w0 = sW0[d * 65 + e];
            float w1 = sW1[d * 65 + e];
            float a = zbuf[sub][0][e];
            float c = zbuf[sub][1][e];
            yr += a * w0 - c * w1;
            yi += a * w1 + c * w0;
        }

        float efr = g_efr[i * 64 + d];
        float efi = g_efi[i * 64 + d];
        float ur = efr * yr + efi * yi;     // U = conj(ef) * y
        float ui = efr * yi - efi * yr;

        if (m == 0)      { g_Uq[row * 128 + d] = ur; g_Uq[row * 128 + 64 + d] = ui; }
        else if (m == 1) { g_UkT[b * 65536 + d * 512 + i]        = ur;
                           g_UkT[b * 65536 + (64 + d) * 512 + i] = ui; }
        else             { g_Uv[row * 128 + d] = ur; g_Uv[row * 128 + 64 + d] = ui;
                           g_V [row * 128 + d] = yr; g_V [row * 128 + 64 + d] = yi; }

        if (m < 2) {
            float v = ur * ur + ui * ui;
#pragma unroll
            for (int off = 16; off > 0; off >>= 1)
                v += __shfl_down_sync(0xffffffffu, v, off);
            if ((tid & 31) == 0) part[tid >> 5] = v;
        }
        __syncthreads();
        if (m < 2 && d == 0) {
            float tot = part[sub * 2] + part[sub * 2 + 1];
            if (m == 0) g_nq[row] = tot;
            else        g_nk[row] = tot;
        }
        __syncthreads();
    }
}

// ============================================================
// K2: tiled fused attention. 16 i-rows/block, 128-wide j tiles.
// grid 64 (b*32 + ib) ; block 256 ; ~108KB dynamic smem
// ============================================================
#define BI 16
#define TJ 128
__global__ void __launch_bounds__(256) k_attn(
    const float* __restrict__ losq, const float* __restrict__ lgsq,
    const float* __restrict__ nfp,  const float* __restrict__ taup,
    float* __restrict__ out)
{
    extern __shared__ float dyn[];
    float* kv  = dyn;                 // 128 e x 128 j  (reused as V tile: 128 j x 128 e)
    float* sQ  = kv + 16384;          // 16 i x 128 e
    float* s   = sQ + 2048;           // 16 i x 512 j
    float* st  = s  + 8192;           // t[512]
    float* snk = st + 512;            // nk[512]

    int tid  = threadIdx.x;
    int b    = blockIdx.x >> 5;
    int ib   = blockIdx.x & 31;
    int i0   = ib * BI;
    int w    = tid >> 5;
    int lane = tid & 31;

    {
        const float4* q4 = (const float4*)(g_Uq + (size_t)(b * 512 + i0) * 128);
        float4* sQ4 = (float4*)sQ;
        for (int k = tid; k < 512; k += 256) sQ4[k] = q4[k];
        for (int k = tid; k < 512; k += 256) { st[k] = g_t[k]; snk[k] = g_nk[b * 512 + k]; }
        for (int k = tid; k < 8192; k += 256) s[k] = -INFINITY;
    }

    float lo   = losq[0] * losq[0];
    float lg   = lgsq[0] * lgsq[0] + EPSf;
    float nf2  = nfp[0] * nfp[0] + EPSf;
    float tau2 = taup[0] * taup[0];

    int r0 = w * 2, r1 = w * 2 + 1;
    int ig0 = i0 + r0, ig1 = i0 + r1;
    int jt_max = (i0 + BI - 1) >> 7;

    __syncthreads();
    float ti0 = st[ig0], ti1 = st[ig1];
    float nq0 = g_nq[b * 512 + ig0], nq1 = g_nq[b * 512 + ig1];

    // ---------- scores ----------
    for (int jt = 0; jt <= jt_max; jt++) {
        int j0 = jt * TJ;
        __syncthreads();
        {
            const float* src = g_UkT + b * 65536 + j0;
            float4* kv4 = (float4*)kv;
            for (int idx = tid; idx < 128 * 32; idx += 256) {
                int e = idx >> 5, jq = idx & 31;
                kv4[e * 32 + jq] = ((const float4*)(src + e * 512))[jq];
            }
        }
        __syncthreads();

        float4 a0 = {0,0,0,0}, a1 = {0,0,0,0};
        const float4* kv4 = (const float4*)kv;
#pragma unroll 8
        for (int e = 0; e < 128; e++) {
            float4 k4 = kv4[e * 32 + lane];
            float q0 = sQ[r0 * 128 + e];
            float q1 = sQ[r1 * 128 + e];
            a0.x += q0 * k4.x; a0.y += q0 * k4.y; a0.z += q0 * k4.z; a0.w += q0 * k4.w;
            a1.x += q1 * k4.x; a1.y += q1 * k4.y; a1.z += q1 * k4.z; a1.w += q1 * k4.w;
        }

        int j = j0 + lane * 4;
        float tj0 = st[j], tj1 = st[j+1], tj2 = st[j+2], tj3 = st[j+3];
        float nk0 = snk[j], nk1 = snk[j+1], nk2 = snk[j+2], nk3 = snk[j+3];

        float4 s0, s1;
        s0.x = (j   <= ig0) ? -tau2 * logf(nf2*(lo*fabsf(ti0-tj0)+lg) + nq0 + nk0 - 2.f*a0.x) : -INFINITY;
        s0.y = (j+1 <= ig0) ? -tau2 * logf(nf2*(lo*fabsf(ti0-tj1)+lg) + nq0 + nk1 - 2.f*a0.y) : -INFINITY;
        s0.z = (j+2 <= ig0) ? -tau2 * logf(nf2*(lo*fabsf(ti0-tj2)+lg) + nq0 + nk2 - 2.f*a0.z) : -INFINITY;
        s0.w = (j+3 <= ig0) ? -tau2 * logf(nf2*(lo*fabsf(ti0-tj3)+lg) + nq0 + nk3 - 2.f*a0.w) : -INFINITY;
        s1.x = (j   <= ig1) ? -tau2 * logf(nf2*(lo*fabsf(ti1-tj0)+lg) + nq1 + nk0 - 2.f*a1.x) : -INFINITY;
        s1.y = (j+1 <= ig1) ? -tau2 * logf(nf2*(lo*fabsf(ti1-tj1)+lg) + nq1 + nk1 - 2.f*a1.y) : -INFINITY;
        s1.z = (j+2 <= ig1) ? -tau2 * logf(nf2*(lo*fabsf(ti1-tj2)+lg) + nq1 + nk2 - 2.f*a1.z) : -INFINITY;
        s1.w = (j+3 <= ig1) ? -tau2 * logf(nf2*(lo*fabsf(ti1-tj3)+lg) + nq1 + nk3 - 2.f*a1.w) : -INFINITY;

        ((float4*)(s + r0 * 512))[j0/4 + lane] = s0;
        ((float4*)(s + r1 * 512))[j0/4 + lane] = s1;
    }
    __syncthreads();

    // ---------- softmax + write A ----------
    for (int rep = 0; rep < 2; rep++) {
        int r = w * 2 + rep;
        int ig = i0 + r;
        float* srow = s + r * 512;
        float mx = -INFINITY;
        for (int k = lane; k < 512; k += 32) mx = fmaxf(mx, srow[k]);
#pragma unroll
        for (int off = 16; off > 0; off >>= 1)
            mx = fmaxf(mx, __shfl_xor_sync(0xffffffffu, mx, off));
        float sum = 0.f;
        for (int k = lane; k < 512; k += 32) {
            float e = expf(srow[k] - mx);
            srow[k] = e;
            sum += e;
        }
#pragma unroll
        for (int off = 16; off > 0; off >>= 1)
            sum += __shfl_xor_sync(0xffffffffu, sum, off);
        float inv = 1.f / sum;
        size_t qoffr = QIJ_OFF + ((size_t)(b * 2 + 0) * 512 + ig) * 512;
        size_t qoffi = QIJ_OFF + ((size_t)(b * 2 + 1) * 512 + ig) * 512;
        for (int k = lane; k < 512; k += 32) {
            float a = srow[k] * inv;
            srow[k] = a;
            out[qoffr + k] = a;
            out[qoffi + k] = 0.f;
        }
    }
    __syncthreads();

    // ---------- AV ----------
    float4 c0 = {0,0,0,0}, c1 = {0,0,0,0};
    for (int jt = 0; jt <= jt_max; jt++) {
        int j0 = jt * TJ;
        __syncthreads();
        {
            const float4* src = (const float4*)(g_Uv + (size_t)(b * 512 + j0) * 128);
            float4* kv4 = (float4*)kv;
            for (int k = tid; k < 128 * 32; k += 256) kv4[k] = src[k];
        }
        __syncthreads();
        const float4* v4 = (const float4*)kv;
#pragma unroll 8
        for (int jj = 0; jj < TJ; jj++) {
            float a0 = s[r0 * 512 + j0 + jj];
            float a1 = s[r1 * 512 + j0 + jj];
            float4 vv = v4[jj * 32 + lane];
            c0.x += a0 * vv.x; c0.y += a0 * vv.y; c0.z += a0 * vv.z; c0.w += a0 * vv.w;
            c1.x += a1 * vv.x; c1.y += a1 * vv.y; c1.z += a1 * vv.z; c1.w += a1 * vv.w;
        }
    }
    ((float4*)(g_e + (size_t)(b * 512 + ig0) * 128))[lane] = c0;
    ((float4*)(g_e + (size_t)(b * 512 + ig1) * 128))[lane] = c1;
}

// ============================================================
// K3: estv / est_latent / P / output projection
// ============================================================
__global__ void __launch_bounds__(256) k_epi(
    const float* __restrict__ Wp, const float* __restrict__ bp,
    const float* __restrict__ etap, float* __restrict__ out)
{
    int tid = threadIdx.x;
    int d   = tid & 63;
    int sub = tid >> 6;

    __shared__ float sW0[64 * 65];
    __shared__ float sW1[64 * 65];
    __shared__ float pbuf[4][2][64];

    for (int idx = tid; idx < 4096; idx += 256) {
        int r = idx >> 6, c = idx & 63;
        sW0[r * 65 + c] = Wp[idx];
        sW1[r * 65 + c] = Wp[4096 + idx];
    }
    float bR = bp[d], bI = bp[64 + d];
    float eta = 1.f / (1.f + expf(-etap[d]));
    float g   = 1.f / (1.f + expf(-eta));
    __syncthreads();

    for (int it = 0; it < 4; it++) {
        int row = blockIdx.x * 16 + it * 4 + sub;
        int b = row >> 9, i = row & 511;

        float efr = g_efr[i * 64 + d];
        float efi = g_efi[i * 64 + d];
        float er = g_e[row * 128 + d];
        float ei = g_e[row * 128 + 64 + d];
        float estr = efr * er - efi * ei;
        float esti = efr * ei + efi * er;

        float elr = (1.f - eta) * g_V[row * 128 + d]      + g * estr;
        float eli = (1.f - eta) * g_V[row * 128 + 64 + d] + g * esti;

        out[EST_OFF + ((size_t)(b * 2 + 0) * 512 + i) * 64 + d] = elr;
        out[EST_OFF + ((size_t)(b * 2 + 1) * 512 + i) * 64 + d] = eli;

        pbuf[sub][0][d] = efr * elr - efi * eli;
        pbuf[sub][1][d] = efr * eli + efi * elr;
        __syncthreads();

        float yr = bR, yi = bI;
#pragma unroll 16
        for (int e = 0; e < 64; e++) {
            float w0 = sW0[d * 65 + e];
            float w1 = sW1[d * 65 + e];
            float a = pbuf[sub][0][e];
            float c = pbuf[sub][1][e];
            yr += a * w0 - c * w1;
            yi += a * w1 + c * w0;
        }
        out[OUT_OFF + ((size_t)(b * 2 + 0) * 512 + i) * 64 + d] = yr;
        out[OUT_OFF + ((size_t)(b * 2 + 1) * 512 + i) * 64 + d] = yi;
        __syncthreads();
    }
}

// ============================================================
// K4: Z_ij_hat_all via TMA bulk stores (bypass STG issue path).
// grid (B*N) ; block 256 ; 64KB dynamic smem (2 bufs x 2 planes x 16KB)
// Per (b,i): 8 chunks of 64 j-rows; each chunk = 16KB contiguous per plane.
// ============================================================
#define ZCH 64
__global__ void __launch_bounds__(256) k_zij(float* __restrict__ out)
{
    extern __shared__ float zb[];     // [2][2][ZCH*64]
    __shared__ __align__(16) float efr[64], efi[64];

    int row = blockIdx.x;
    int b = row >> 9, i = row & 511;
    int tid = threadIdx.x;

    if (tid < 64)            efr[tid]      = g_efr[i * 64 + tid];
    else if (tid < 128)      efi[tid - 64] = g_efi[i * 64 + (tid - 64)];
    __syncthreads();

    const float4* uv4 = (const float4*)(g_Uv + (size_t)b * 512 * 128);
    float* zr_base = out + Z_OFF + ((size_t)(b * 2 + 0) * 512 + i) * 32768;
    float* zi_base = out + Z_OFF + ((size_t)(b * 2 + 1) * 512 + i) * 32768;

#pragma unroll 1
    for (int c = 0; c < 8; c++) {
        int j0 = c * ZCH;
        float* bufR = zb + (c & 1) * 8192;
        float* bufI = bufR + 4096;

        if (c >= 2 && tid == 0)
            asm volatile("cp.async.bulk.wait_group.read 1;" ::: "memory");
        __syncthreads();

        float4* bR4 = (float4*)bufR;
        float4* bI4 = (float4*)bufI;
#pragma unroll
        for (int k = tid; k < ZCH * 16; k += 256) {
            int j  = k >> 4;
            int d4 = k & 15;
            int d  = d4 << 2;
            float4 vr = uv4[(size_t)(j0 + j) * 32 + d4];
            float4 vi = uv4[(size_t)(j0 + j) * 32 + 16 + d4];
            float e0 = efr[d],     f0 = efi[d];
            float e1 = efr[d + 1], f1 = efi[d + 1];
            float e2 = efr[d + 2], f2 = efi[d + 2];
            float e3 = efr[d + 3], f3 = efi[d + 3];
            float4 zr, zi;
            zr.x = e0 * vr.x - f0 * vi.x;  zi.x = e0 * vi.x + f0 * vr.x;
            zr.y = e1 * vr.y - f1 * vi.y;  zi.y = e1 * vi.y + f1 * vr.y;
            zr.z = e2 * vr.z - f2 * vi.z;  zi.z = e2 * vi.z + f2 * vr.z;
            zr.w = e3 * vr.w - f3 * vi.w;  zi.w = e3 * vi.w + f3 * vr.w;
            bR4[k] = zr;
            bI4[k] = zi;
        }
        __syncthreads();

        if (tid == 0) {
            asm volatile("fence.proxy.async.shared::cta;" ::: "memory");
            uint32_t sR = smem_u32(bufR);
            uint32_t sI = smem_u32(bufI);
            asm volatile("cp.async.bulk.global.shared::cta.bulk_group [%0], [%1], %2;"
                         :: "l"(zr_base + (size_t)j0 * 64), "r"(sR), "r"(ZCH * 64 * 4) : "memory");
            asm volatile("cp.async.bulk.global.shared::cta.bulk_group [%0], [%1], %2;"
                         :: "l"(zi_base + (size_t)j0 * 64), "r"(sI), "r"(ZCH * 64 * 4) : "memory");
            asm volatile("cp.async.bulk.commit_group;" ::: "memory");
        }
    }
    if (tid == 0)
        asm volatile("cp.async.bulk.wait_group.read 0;" ::: "memory");
}

// ============================================================
extern "C" void kernel_launch(void* const* d_in, const int* in_sizes, int n_in,
                              void* d_out, int out_size)
{
    const float* Zq   = (const float*)d_in[0];
    const float* Zk   = (const float*)d_in[1];
    const float* Zv   = (const float*)d_in[2];
    const float* tm   = (const float*)d_in[3];
    const float* Wq   = (const float*)d_in[4];
    const float* bq   = (const float*)d_in[5];
    const float* Wk   = (const float*)d_in[6];
    const float* bk   = (const float*)d_in[7];
    const float* Wv   = (const float*)d_in[8];
    const float* bv   = (const float*)d_in[9];
    const float* Wp   = (const float*)d_in[10];
    const float* bp   = (const float*)d_in[11];
    const float* lv   = (const float*)d_in[12];
    const float* losq = (const float*)d_in[13];
    const float* lgsq = (const float*)d_in[14];
    const float* nf   = (const float*)d_in[15];
    const float* tau  = (const float*)d_in[16];
    const float* etap = (const float*)d_in[17];
    float* out = (float*)d_out;

    static cudaStream_t s_z = nullptr;
    static cudaEvent_t ev_fork = nullptr, ev_join = nullptr;
    static const int attn_smem = (16384 + 2048 + 8192 + 512 + 512) * 4;
    static const int zij_smem  = 2 * 2 * ZCH * 64 * 4;   // 64KB
    if (s_z == nullptr) {
        cudaStreamCreateWithFlags(&s_z, cudaStreamNonBlocking);
        cudaEventCreateWithFlags(&ev_fork, cudaEventDisableTiming);
        cudaEventCreateWithFlags(&ev_join, cudaEventDisableTiming);
        cudaFuncSetAttribute(k_attn, cudaFuncAttributeMaxDynamicSharedMemorySize, attn_smem);
        cudaFuncSetAttribute(k_zij,  cudaFuncAttributeMaxDynamicSharedMemorySize, zij_smem);
    }

    k_setup<<<64, 512>>>(tm, lv, out + LH_OFF);
    k_proj<<<dim3(128, 3), 256>>>(Zq, Zk, Zv, Wq, bq, Wk, bk, Wv, bv);

    // fork: Z-plane TMA writer overlaps with attention + epilogue
    cudaEventRecord(ev_fork, 0);
    cudaStreamWaitEvent(s_z, ev_fork, 0);
    k_zij<<<Bn * Nn, 256, zij_smem, s_z>>>(out);
    cudaEventRecord(ev_join, s_z);

    k_attn<<<64, 256, attn_smem>>>(losq, lgsq, nf, tau, out);
    k_epi<<<64, 256>>>(Wp, bp, etap, out);

    cudaStreamWaitEvent(0, ev_join, 0);
}

// round 5
// speedup vs baseline: 1.0045x; 1.0045x over previous
#include <cuda_runtime.h>
#include <math.h>
#include <stdint.h>

#define Bn 2
#define Nn 512
#define Dn 64
#define EPSf 1e-8f

#define EST_OFF  ((size_t)0)
#define OUT_OFF  ((size_t)131072)
#define QIJ_OFF  ((size_t)262144)
#define Z_OFF    ((size_t)1310720)
#define LH_OFF   ((size_t)68419584)

// ---- device scratch ----
__device__ __align__(16) float g_t[Nn];
__device__ __align__(16) float g_efr[Nn*Dn];
__device__ __align__(16) float g_efi[Nn*Dn];
__device__ __align__(16) float g_Uq[Bn*Nn*128];      // [row][e]  e<64 real, e>=64 imag
__device__ __align__(16) float g_UkT[Bn*128*Nn];     // [b][e][j]
__device__ __align__(16) float g_Uv[Bn*Nn*128];      // [row][e]
__device__ __align__(16) float g_V [Bn*Nn*128];      // [row][e]
__device__ __align__(16) float g_e [Bn*Nn*128];      // er | ei combined
__device__ __align__(16) float g_s [Bn*Nn*Nn];       // scores / probs scratch (2MB)
__device__ float g_nq[Bn*Nn];
__device__ float g_nk[Bn*Nn];

// causal tile map for k_scores: 20 (it,jt) pairs per b
__device__ const int SC_IT[20] = {0,1,2,2,3,3,4,4,4,5,5,5,6,6,6,6,7,7,7,7};
__device__ const int SC_JT[20] = {0,0,0,1,0,1,0,1,2,0,1,2,0,1,2,3,0,1,2,3};

// ============================================================
// K0: t, e^{i phi} tables, lambda_h output
// ============================================================
__global__ void k_setup(const float* __restrict__ tm,
                        const float* __restrict__ lv,
                        float* __restrict__ out_lh)
{
    int idx = blockIdx.x * blockDim.x + threadIdx.x;   // 0..32767
    int i = idx >> 6;
    int d = idx & 63;
    float denom = tm[Nn - 1] - tm[0];
    float ti = tm[i] / denom;
    float lam = (d < 32) ? lv[d] : -lv[d - 32];
    float sph, cph;
    sincosf(ti * lam, &sph, &cph);
    g_efr[idx] = cph;
    g_efi[idx] = sph;
    if (d == 0) g_t[i] = ti;
    if (idx < 128) {
        float v;
        if (idx < 64) v = 0.f;
        else {
            int k = idx - 64;
            v = (k < 32) ? lv[k] : -lv[k - 32];
        }
        out_lh[idx] = v;
    }
}

// ============================================================
// K1: complex projections + twist. grid (128,3) ; block 256 ; 8 rows/block
// ============================================================
__global__ void __launch_bounds__(256) k_proj(
    const float* __restrict__ Zq, const float* __restrict__ Zk,
    const float* __restrict__ Zv,
    const float* __restrict__ Wq, const float* __restrict__ bq,
    const float* __restrict__ Wk, const float* __restrict__ bk,
    const float* __restrict__ Wv, const float* __restrict__ bv)
{
    int m   = blockIdx.y;
    int tid = threadIdx.x;
    int d   = tid & 63;
    int sub = tid >> 6;

    const float* Z  = (m == 0) ? Zq : (m == 1) ? Zk : Zv;
    const float* W  = (m == 0) ? Wq : (m == 1) ? Wk : Wv;
    const float* bb = (m == 0) ? bq : (m == 1) ? bk : bv;

    __shared__ float sW0[64 * 65];
    __shared__ float sW1[64 * 65];
    __shared__ float zbuf[4][2][64];
    __shared__ float part[8];

    for (int idx = tid; idx < 4096; idx += 256) {
        int r = idx >> 6, c = idx & 63;
        sW0[r * 65 + c] = W[idx];
        sW1[r * 65 + c] = W[4096 + idx];
    }
    float bR = bb[d], bI = bb[64 + d];
    __syncthreads();

#pragma unroll
    for (int it = 0; it < 2; it++) {
        int row = blockIdx.x * 8 + it * 4 + sub;
        int b = row >> 9, i = row & 511;

        zbuf[sub][0][d] = Z[((size_t)(b * 2 + 0) * Nn + i) * Dn + d];
        zbuf[sub][1][d] = Z[((size_t)(b * 2 + 1) * Nn + i) * Dn + d];
        __syncthreads();

        float yr = bR, yi = bI;
#pragma unroll 16
        for (int e = 0; e < 64; e++) {
            float w0 = sW0[d * 65 + e];
            float w1 = sW1[d * 65 + e];
            float a = zbuf[sub][0][e];
            float c = zbuf[sub][1][e];
            yr += a * w0 - c * w1;
            yi += a * w1 + c * w0;
        }

        float efr = g_efr[i * 64 + d];
        float efi = g_efi[i * 64 + d];
        float ur = efr * yr + efi * yi;
        float ui = efr * yi - efi * yr;

        if (m == 0)      { g_Uq[row * 128 + d] = ur; g_Uq[row * 128 + 64 + d] = ui; }
        else if (m == 1) { g_UkT[b * 65536 + d * 512 + i]        = ur;
                           g_UkT[b * 65536 + (64 + d) * 512 + i] = ui; }
        else             { g_Uv[row * 128 + d] = ur; g_Uv[row * 128 + 64 + d] = ui;
                           g_V [row * 128 + d] = yr; g_V [row * 128 + 64 + d] = yi; }

        if (m < 2) {
            float v = ur * ur + ui * ui;
#pragma unroll
            for (int off = 16; off > 0; off >>= 1)
                v += __shfl_down_sync(0xffffffffu, v, off);
            if ((tid & 31) == 0) part[tid >> 5] = v;
        }
        __syncthreads();
        if (m < 2 && d == 0) {
            float tot = part[sub * 2] + part[sub * 2 + 1];
            if (m == 0) g_nq[row] = tot;
            else        g_nk[row] = tot;
        }
        __syncthreads();
    }
}

// ============================================================
// K2a: scores GEMM. 64i x 128j tiles, thread tile 4i x 8j.
// grid 40 ; block 256 ; ~98KB smem
// ============================================================
__global__ void __launch_bounds__(256) k_scores(
    const float* __restrict__ losq, const float* __restrict__ lgsq,
    const float* __restrict__ nfp,  const float* __restrict__ taup)
{
    extern __shared__ float sm[];
    float* sQT = sm;              // [128e][68]  (64 i + pad)
    float* sK  = sm + 128 * 68;   // [128e][128j]

    int bid = blockIdx.x;
    int b   = bid / 20;
    int t20 = bid % 20;
    int it  = SC_IT[t20], jt = SC_JT[t20];
    int i0  = it * 64, j0 = jt * 128;

    int tid = threadIdx.x;
    int tx  = tid & 15;      // j group (8 j each)
    int ty  = tid >> 4;      // i group (4 i each)

    // stage Q^T [e][i]
    {
        const float4* q4 = (const float4*)(g_Uq + (size_t)(b * 512 + i0) * 128);
        for (int idx = tid; idx < 64 * 32; idx += 256) {
            int r = idx >> 5, e4 = idx & 31;
            float4 v = q4[r * 32 + e4];
            int e = e4 * 4;
            sQT[(e + 0) * 68 + r] = v.x;
            sQT[(e + 1) * 68 + r] = v.y;
            sQT[(e + 2) * 68 + r] = v.z;
            sQT[(e + 3) * 68 + r] = v.w;
        }
    }
    // stage K [e][j0..j0+127]
    {
        const float* src = g_UkT + b * 65536 + j0;
        for (int idx = tid; idx < 128 * 32; idx += 256) {
            int e = idx >> 5, j4 = idx & 31;
            ((float4*)(sK + e * 128))[j4] = ((const float4*)(src + e * 512))[j4];
        }
    }
    __syncthreads();

    float c[4][8];
#pragma unroll
    for (int a = 0; a < 4; a++)
#pragma unroll
        for (int q = 0; q < 8; q++) c[a][q] = 0.f;

#pragma unroll 4
    for (int e = 0; e < 128; e++) {
        float4 aq = *(const float4*)(sQT + e * 68 + ty * 4);
        float4 b0 = *(const float4*)(sK + e * 128 + tx * 8);
        float4 b1 = *(const float4*)(sK + e * 128 + tx * 8 + 4);
        float av[4] = {aq.x, aq.y, aq.z, aq.w};
        float bv[8] = {b0.x, b0.y, b0.z, b0.w, b1.x, b1.y, b1.z, b1.w};
#pragma unroll
        for (int a = 0; a < 4; a++)
#pragma unroll
            for (int q = 0; q < 8; q++)
                c[a][q] += av[a] * bv[q];
    }

    // epilogue: R-term + log + causal mask -> g_s
    float lo   = losq[0] * losq[0];
    float lg   = lgsq[0] * lgsq[0] + EPSf;
    float nf2  = nfp[0] * nfp[0] + EPSf;
    float tau2 = taup[0] * taup[0];

    int jb = j0 + tx * 8;
    float tj[8], nk[8];
#pragma unroll
    for (int q = 0; q < 8; q++) {
        tj[q] = g_t[jb + q];
        nk[q] = g_nk[b * 512 + jb + q];
    }

#pragma unroll
    for (int a = 0; a < 4; a++) {
        int i = i0 + ty * 4 + a;
        float ti = g_t[i];
        float nq = g_nq[b * 512 + i];
        float r[8];
#pragma unroll
        for (int q = 0; q < 8; q++) {
            float base = nf2 * (lo * fabsf(ti - tj[q]) + lg) + nq + nk[q] - 2.f * c[a][q];
            r[q] = (jb + q <= i) ? (-tau2 * logf(base)) : -INFINITY;
        }
        float* dst = g_s + ((size_t)(b * 512 + i) * 512 + jb);
        *(float4*)dst       = make_float4(r[0], r[1], r[2], r[3]);
        *(float4*)(dst + 4) = make_float4(r[4], r[5], r[6], r[7]);
    }
}

// ============================================================
// K2b: softmax rows + write A plane (+ zero imag) + normalized probs to g_s
// grid 1024 ; block 256
// ============================================================
__global__ void __launch_bounds__(256) k_softmax(float* __restrict__ out)
{
    int row = blockIdx.x;
    int b = row >> 9, i = row & 511;
    int tid = threadIdx.x;

    __shared__ float red[256];
    float* srow = g_s + (size_t)row * 512;

    float v0 = (tid     <= i) ? srow[tid]       : -INFINITY;
    float v1 = (tid+256 <= i) ? srow[tid + 256] : -INFINITY;

    red[tid] = fmaxf(v0, v1);
    __syncthreads();
    for (int st = 128; st > 0; st >>= 1) {
        if (tid < st) red[tid] = fmaxf(red[tid], red[tid + st]);
        __syncthreads();
    }
    float mx = red[0];
    __syncthreads();

    float e0 = (tid     <= i) ? expf(v0 - mx) : 0.f;
    float e1 = (tid+256 <= i) ? expf(v1 - mx) : 0.f;
    red[tid] = e0 + e1;
    __syncthreads();
    for (int st = 128; st > 0; st >>= 1) {
        if (tid < st) red[tid] += red[tid + st];
        __syncthreads();
    }
    float inv = 1.f / red[0];

    float a0 = e0 * inv;
    float a1 = e1 * inv;
    srow[tid]       = a0;
    srow[tid + 256] = a1;
    size_t qoffr = QIJ_OFF + ((size_t)(b * 2 + 0) * 512 + i) * 512;
    size_t qoffi = QIJ_OFF + ((size_t)(b * 2 + 1) * 512 + i) * 512;
    out[qoffr + tid]       = a0;
    out[qoffr + tid + 256] = a1;
    out[qoffi + tid]       = 0.f;
    out[qoffi + tid + 256] = 0.f;
}

// ============================================================
// K2c: AV GEMM. output 64i x 128e tiles, k over causal 128-j chunks.
// grid 16 (b*8+it) ; block 256 ; ~98KB smem
// ============================================================
__global__ void __launch_bounds__(256) k_av()
{
    extern __shared__ float sm[];
    float* sAT = sm;              // [128j][68]  (64 i + pad)
    float* sV  = sm + 128 * 68;   // [128j][128e]

    int bid = blockIdx.x;
    int b  = bid >> 3;
    int it = bid & 7;
    int i0 = it * 64;
    int nch = (it >> 1) + 1;      // causal chunk count

    int tid = threadIdx.x;
    int tx  = tid & 15;           // e group (8)
    int ty  = tid >> 4;           // i group (4)

    float c[4][8];
#pragma unroll
    for (int a = 0; a < 4; a++)
#pragma unroll
        for (int q = 0; q < 8; q++) c[a][q] = 0.f;

    for (int ch = 0; ch < nch; ch++) {
        int jc = ch * 128;
        __syncthreads();
        // stage A^T [j][i]
        for (int idx = tid; idx < 64 * 32; idx += 256) {
            int r = idx >> 5, j4 = idx & 31;
            float4 v = *(const float4*)(g_s + ((size_t)(b * 512 + i0 + r) * 512 + jc + j4 * 4));
            int j = j4 * 4;
            sAT[(j + 0) * 68 + r] = v.x;
            sAT[(j + 1) * 68 + r] = v.y;
            sAT[(j + 2) * 68 + r] = v.z;
            sAT[(j + 3) * 68 + r] = v.w;
        }
        // stage V [j][e]
        {
            const float4* src = (const float4*)(g_Uv + (size_t)(b * 512 + jc) * 128);
            for (int idx = tid; idx < 128 * 32; idx += 256)
                ((float4*)sV)[idx] = src[idx];
        }
        __syncthreads();

#pragma unroll 4
        for (int j = 0; j < 128; j++) {
            float4 aa = *(const float4*)(sAT + j * 68 + ty * 4);
            float4 b0 = *(const float4*)(sV + j * 128 + tx * 8);
            float4 b1 = *(const float4*)(sV + j * 128 + tx * 8 + 4);
            float av[4] = {aa.x, aa.y, aa.z, aa.w};
            float bv[8] = {b0.x, b0.y, b0.z, b0.w, b1.x, b1.y, b1.z, b1.w};
#pragma unroll
            for (int a = 0; a < 4; a++)
#pragma unroll
                for (int q = 0; q < 8; q++)
                    c[a][q] += av[a] * bv[q];
        }
    }

#pragma unroll
    for (int a = 0; a < 4; a++) {
        float* dst = g_e + (size_t)(b * 512 + i0 + ty * 4 + a) * 128 + tx * 8;
        *(float4*)dst       = make_float4(c[a][0], c[a][1], c[a][2], c[a][3]);
        *(float4*)(dst + 4) = make_float4(c[a][4], c[a][5], c[a][6], c[a][7]);
    }
}

// ============================================================
// K3: estv / est_latent / P / output projection
// ============================================================
__global__ void __launch_bounds__(256) k_epi(
    const float* __restrict__ Wp, const float* __restrict__ bp,
    const float* __restrict__ etap, float* __restrict__ out)
{
    int tid = threadIdx.x;
    int d   = tid & 63;
    int sub = tid >> 6;

    __shared__ float sW0[64 * 65];
    __shared__ float sW1[64 * 65];
    __shared__ float pbuf[4][2][64];

    for (int idx = tid; idx < 4096; idx += 256) {
        int r = idx >> 6, c = idx & 63;
        sW0[r * 65 + c] = Wp[idx];
        sW1[r * 65 + c] = Wp[4096 + idx];
    }
    float bR = bp[d], bI = bp[64 + d];
    float eta = 1.f / (1.f + expf(-etap[d]));
    float g   = 1.f / (1.f + expf(-eta));
    __syncthreads();

    for (int it = 0; it < 4; it++) {
        int row = blockIdx.x * 16 + it * 4 + sub;
        int b = row >> 9, i = row & 511;

        float efr = g_efr[i * 64 + d];
        float efi = g_efi[i * 64 + d];
        float er = g_e[row * 128 + d];
        float ei = g_e[row * 128 + 64 + d];
        float estr = efr * er - efi * ei;
        float esti = efr * ei + efi * er;

        float elr = (1.f - eta) * g_V[row * 128 + d]      + g * estr;
        float eli = (1.f - eta) * g_V[row * 128 + 64 + d] + g * esti;

        out[EST_OFF + ((size_t)(b * 2 + 0) * 512 + i) * 64 + d] = elr;
        out[EST_OFF + ((size_t)(b * 2 + 1) * 512 + i) * 64 + d] = eli;

        pbuf[sub][0][d] = efr * elr - efi * eli;
        pbuf[sub][1][d] = efr * eli + efi * elr;
        __syncthreads();

        float yr = bR, yi = bI;
#pragma unroll 16
        for (int e = 0; e < 64; e++) {
            float w0 = sW0[d * 65 + e];
            float w1 = sW1[d * 65 + e];
            float a = pbuf[sub][0][e];
            float c = pbuf[sub][1][e];
            yr += a * w0 - c * w1;
            yi += a * w1 + c * w0;
        }
        out[OUT_OFF + ((size_t)(b * 2 + 0) * 512 + i) * 64 + d] = yr;
        out[OUT_OFF + ((size_t)(b * 2 + 1) * 512 + i) * 64 + d] = yi;
        __syncthreads();
    }
}

// ============================================================
// K4: Z_ij_hat_all — 268 MB streaming write (proven __stcs version).
// grid (B*N) ; block 256
// ============================================================
__global__ void __launch_bounds__(256) k_zij(float* __restrict__ out)
{
    int row = blockIdx.x;
    int b = row >> 9, i = row & 511;
    int tid = threadIdx.x;

    __shared__ __align__(16) float efr[64], efi[64];
    if (tid < 64)            efr[tid]      = g_efr[i * 64 + tid];
    else if (tid < 128)      efi[tid - 64] = g_efi[i * 64 + (tid - 64)];
    __syncthreads();

    const float4* uv4 = (const float4*)(g_Uv + (size_t)b * 512 * 128);
    float4* zr4 = (float4*)(out + Z_OFF + ((size_t)(b * 2 + 0) * 512 + i) * 512 * 64);
    float4* zi4 = (float4*)(out + Z_OFF + ((size_t)(b * 2 + 1) * 512 + i) * 512 * 64);

    for (int k = tid; k < 512 * 16; k += 256) {
        int j  = k >> 4;
        int d4 = k & 15;
        int d  = d4 << 2;
        float4 vr = uv4[j * 32 + d4];
        float4 vi = uv4[j * 32 + 16 + d4];
        float e0 = efr[d],     f0 = efi[d];
        float e1 = efr[d + 1], f1 = efi[d + 1];
        float e2 = efr[d + 2], f2 = efi[d + 2];
        float e3 = efr[d + 3], f3 = efi[d + 3];
        float4 zr, zi;
        zr.x = e0 * vr.x - f0 * vi.x;  zi.x = e0 * vi.x + f0 * vr.x;
        zr.y = e1 * vr.y - f1 * vi.y;  zi.y = e1 * vi.y + f1 * vr.y;
        zr.z = e2 * vr.z - f2 * vi.z;  zi.z = e2 * vi.z + f2 * vr.z;
        zr.w = e3 * vr.w - f3 * vi.w;  zi.w = e3 * vi.w + f3 * vr.w;
        __stcs(&zr4[k], zr);
        __stcs(&zi4[k], zi);
    }
}

// ============================================================
extern "C" void kernel_launch(void* const* d_in, const int* in_sizes, int n_in,
                              void* d_out, int out_size)
{
    const float* Zq   = (const float*)d_in[0];
    const float* Zk   = (const float*)d_in[1];
    const float* Zv   = (const float*)d_in[2];
    const float* tm   = (const float*)d_in[3];
    const float* Wq   = (const float*)d_in[4];
    const float* bq   = (const float*)d_in[5];
    const float* Wk   = (const float*)d_in[6];
    const float* bk   = (const float*)d_in[7];
    const float* Wv   = (const float*)d_in[8];
    const float* bv   = (const float*)d_in[9];
    const float* Wp   = (const float*)d_in[10];
    const float* bp   = (const float*)d_in[11];
    const float* lv   = (const float*)d_in[12];
    const float* losq = (const float*)d_in[13];
    const float* lgsq = (const float*)d_in[14];
    const float* nf   = (const float*)d_in[15];
    const float* tau  = (const float*)d_in[16];
    const float* etap = (const float*)d_in[17];
    float* out = (float*)d_out;

    static cudaStream_t s_z = nullptr;
    static cudaEvent_t ev_fork = nullptr, ev_join = nullptr;
    static const int gemm_smem = (128 * 68 + 128 * 128) * 4;   // ~98KB
    if (s_z == nullptr) {
        cudaStreamCreateWithFlags(&s_z, cudaStreamNonBlocking);
        cudaEventCreateWithFlags(&ev_fork, cudaEventDisableTiming);
        cudaEventCreateWithFlags(&ev_join, cudaEventDisableTiming);
        cudaFuncSetAttribute(k_scores, cudaFuncAttributeMaxDynamicSharedMemorySize, gemm_smem);
        cudaFuncSetAttribute(k_av,     cudaFuncAttributeMaxDynamicSharedMemorySize, gemm_smem);
    }

    k_setup<<<64, 512>>>(tm, lv, out + LH_OFF);
    k_proj<<<dim3(128, 3), 256>>>(Zq, Zk, Zv, Wq, bq, Wk, bk, Wv, bv);

    // fork: Z-plane writer overlaps with attention chain + epilogue
    cudaEventRecord(ev_fork, 0);
    cudaStreamWaitEvent(s_z, ev_fork, 0);
    k_zij<<<Bn * Nn, 256, 0, s_z>>>(out);
    cudaEventRecord(ev_join, s_z);

    k_scores<<<40, 256, gemm_smem>>>(losq, lgsq, nf, tau);
    k_softmax<<<Bn * Nn, 256>>>(out);
    k_av<<<16, 256, gemm_smem>>>();
    k_epi<<<64, 256>>>(Wp, bp, etap, out);

    cudaStreamWaitEvent(0, ev_join, 0);
}

// round 6
// speedup vs baseline: 1.6571x; 1.6497x over previous
#include <cuda_runtime.h>
#include <math.h>
#include <stdint.h>

#define Bn 2
#define Nn 512
#define Dn 64
#define EPSf 1e-8f

#define EST_OFF  ((size_t)0)
#define OUT_OFF  ((size_t)131072)
#define QIJ_OFF  ((size_t)262144)
#define Z_OFF    ((size_t)1310720)
#define LH_OFF   ((size_t)68419584)

// ---- device scratch ----
__device__ __align__(16) float g_t[Nn];
__device__ __align__(16) float g_efr[Nn*Dn];
__device__ __align__(16) float g_efi[Nn*Dn];
__device__ __align__(16) float g_Uq[Bn*Nn*128];      // [row][e]  e<64 real, e>=64 imag
__device__ __align__(16) float g_UkT[Bn*128*Nn];     // [b][e][j]
__device__ __align__(16) float g_Uv[Bn*Nn*128];      // [row][e]
__device__ __align__(16) float g_V [Bn*Nn*128];      // [row][e]
__device__ __align__(16) float g_e [Bn*Nn*128];      // er | ei combined
__device__ __align__(16) float g_eP[4][Bn*Nn*128];   // split-k partials (2MB)
__device__ __align__(16) float g_s [Bn*Nn*Nn];       // scores / probs scratch (2MB)
__device__ float g_nq[Bn*Nn];
__device__ float g_nk[Bn*Nn];

// causal 64x64 tile map for k_scores: 36 (it,jt) pairs per b
__device__ const int SC_IT[36] = {0,1,1,2,2,2,3,3,3,3,4,4,4,4,4,5,5,5,5,5,5,
                                  6,6,6,6,6,6,6,7,7,7,7,7,7,7,7};
__device__ const int SC_JT[36] = {0,0,1,0,1,2,0,1,2,3,0,1,2,3,4,0,1,2,3,4,5,
                                  0,1,2,3,4,5,6,0,1,2,3,4,5,6,7};
// split-k map for k_av: 20 (it,ch) pairs per b (64-i tiles, 128-j chunks)
__device__ const int AV_IT[20] = {0,1,2,2,3,3,4,4,4,5,5,5,6,6,6,6,7,7,7,7};
__device__ const int AV_CH[20] = {0,0,0,1,0,1,0,1,2,0,1,2,0,1,2,3,0,1,2,3};

// ============================================================
// K0: t, e^{i phi} tables, lambda_h output
// ============================================================
__global__ void k_setup(const float* __restrict__ tm,
                        const float* __restrict__ lv,
                        float* __restrict__ out_lh)
{
    int idx = blockIdx.x * blockDim.x + threadIdx.x;   // 0..32767
    int i = idx >> 6;
    int d = idx & 63;
    float denom = tm[Nn - 1] - tm[0];
    float ti = tm[i] / denom;
    float lam = (d < 32) ? lv[d] : -lv[d - 32];
    float sph, cph;
    sincosf(ti * lam, &sph, &cph);
    g_efr[idx] = cph;
    g_efi[idx] = sph;
    if (d == 0) g_t[i] = ti;
    if (idx < 128) {
        float v;
        if (idx < 64) v = 0.f;
        else {
            int k = idx - 64;
            v = (k < 32) ? lv[k] : -lv[k - 32];
        }
        out_lh[idx] = v;
    }
}

// ============================================================
// K1: complex projections + twist. grid (256,3) ; block 256 ; 4 rows/block
// ============================================================
__global__ void __launch_bounds__(256) k_proj(
    const float* __restrict__ Zq, const float* __restrict__ Zk,
    const float* __restrict__ Zv,
    const float* __restrict__ Wq, const float* __restrict__ bq,
    const float* __restrict__ Wk, const float* __restrict__ bk,
    const float* __restrict__ Wv, const float* __restrict__ bv)
{
    int m   = blockIdx.y;
    int tid = threadIdx.x;
    int d   = tid & 63;
    int sub = tid >> 6;

    const float* Z  = (m == 0) ? Zq : (m == 1) ? Zk : Zv;
    const float* W  = (m == 0) ? Wq : (m == 1) ? Wk : Wv;
    const float* bb = (m == 0) ? bq : (m == 1) ? bk : bv;

    __shared__ float sW0[64 * 65];
    __shared__ float sW1[64 * 65];
    __shared__ float zbuf[4][2][64];
    __shared__ float part[8];

    // stage weights: float4 reads, scalar stores into padded rows
    {
        const float4* W04 = (const float4*)W;
        const float4* W14 = (const float4*)(W + 4096);
#pragma unroll
        for (int idx4 = tid; idx4 < 1024; idx4 += 256) {
            int r = idx4 >> 4, c = (idx4 & 15) * 4;
            float4 v0 = W04[idx4];
            float4 v1 = W14[idx4];
            float* p0 = sW0 + r * 65 + c;
            float* p1 = sW1 + r * 65 + c;
            p0[0] = v0.x; p0[1] = v0.y; p0[2] = v0.z; p0[3] = v0.w;
            p1[0] = v1.x; p1[1] = v1.y; p1[2] = v1.z; p1[3] = v1.w;
        }
    }
    float bR = bb[d], bI = bb[64 + d];

    int row = blockIdx.x * 4 + sub;     // 0..1023
    int b = row >> 9, i = row & 511;

    zbuf[sub][0][d] = Z[((size_t)(b * 2 + 0) * Nn + i) * Dn + d];
    zbuf[sub][1][d] = Z[((size_t)(b * 2 + 1) * Nn + i) * Dn + d];
    __syncthreads();

    float yr = bR, yi = bI;
#pragma unroll 16
    for (int e = 0; e < 64; e++) {
        float w0 = sW0[d * 65 + e];
        float w1 = sW1[d * 65 + e];
        float a = zbuf[sub][0][e];
        float c = zbuf[sub][1][e];
        yr += a * w0 - c * w1;
        yi += a * w1 + c * w0;
    }

    float efr = g_efr[i * 64 + d];
    float efi = g_efi[i * 64 + d];
    float ur = efr * yr + efi * yi;
    float ui = efr * yi - efi * yr;

    if (m == 0)      { g_Uq[row * 128 + d] = ur; g_Uq[row * 128 + 64 + d] = ui; }
    else if (m == 1) { g_UkT[b * 65536 + d * 512 + i]        = ur;
                       g_UkT[b * 65536 + (64 + d) * 512 + i] = ui; }
    else             { g_Uv[row * 128 + d] = ur; g_Uv[row * 128 + 64 + d] = ui;
                       g_V [row * 128 + d] = yr; g_V [row * 128 + 64 + d] = yi; }

    if (m < 2) {
        float v = ur * ur + ui * ui;
#pragma unroll
        for (int off = 16; off > 0; off >>= 1)
            v += __shfl_down_sync(0xffffffffu, v, off);
        if ((tid & 31) == 0) part[tid >> 5] = v;
        __syncthreads();
        if (d == 0) {
            float tot = part[sub * 2] + part[sub * 2 + 1];
            if (m == 0) g_nq[row] = tot;
            else        g_nk[row] = tot;
        }
    }
}

// ============================================================
// K2a: scores GEMM. 64i x 64j tiles, thread tile 4i x 4j. grid 72.
// ============================================================
__global__ void __launch_bounds__(256) k_scores(
    const float* __restrict__ losq, const float* __restrict__ lgsq,
    const float* __restrict__ nfp,  const float* __restrict__ taup)
{
    extern __shared__ float sm[];
    float* sQ = sm;               // [64 i][132]  (128 e + pad)
    float* sK = sm + 64 * 132;    // [128 e][68]  (64 j + pad)

    int bid = blockIdx.x;
    int b   = bid / 36;
    int t36 = bid % 36;
    int it  = SC_IT[t36], jt = SC_JT[t36];
    int i0  = it * 64, j0 = jt * 64;

    int tid = threadIdx.x;
    int tx  = tid & 15;      // j group (4 each)
    int ty  = tid >> 4;      // i group (4 each)

    // stage Q [i][e]
    {
        const float4* q4 = (const float4*)(g_Uq + (size_t)(b * 512 + i0) * 128);
        for (int idx4 = tid; idx4 < 64 * 32; idx4 += 256) {
            int r = idx4 >> 5, c = (idx4 & 31) * 4;
            float4 v = q4[idx4];
            float* p = sQ + r * 132 + c;
            p[0] = v.x; p[1] = v.y; p[2] = v.z; p[3] = v.w;
        }
    }
    // stage K [e][j]
    {
        const float* src = g_UkT + b * 65536 + j0;
        for (int idx4 = tid; idx4 < 128 * 16; idx4 += 256) {
            int e = idx4 >> 4, c = (idx4 & 15) * 4;
            float4 v = ((const float4*)(src + e * 512))[idx4 & 15];
            float* p = sK + e * 68 + c;
            p[0] = v.x; p[1] = v.y; p[2] = v.z; p[3] = v.w;
        }
    }
    __syncthreads();

    float c[4][4];
#pragma unroll
    for (int a = 0; a < 4; a++)
#pragma unroll
        for (int q = 0; q < 4; q++) c[a][q] = 0.f;

#pragma unroll 8
    for (int e = 0; e < 128; e++) {
        float4 kk = *(const float4*)(sK + e * 68 + tx * 4);
        float a0 = sQ[(ty * 4 + 0) * 132 + e];
        float a1 = sQ[(ty * 4 + 1) * 132 + e];
        float a2 = sQ[(ty * 4 + 2) * 132 + e];
        float a3 = sQ[(ty * 4 + 3) * 132 + e];
        c[0][0] += a0 * kk.x; c[0][1] += a0 * kk.y; c[0][2] += a0 * kk.z; c[0][3] += a0 * kk.w;
        c[1][0] += a1 * kk.x; c[1][1] += a1 * kk.y; c[1][2] += a1 * kk.z; c[1][3] += a1 * kk.w;
        c[2][0] += a2 * kk.x; c[2][1] += a2 * kk.y; c[2][2] += a2 * kk.z; c[2][3] += a2 * kk.w;
        c[3][0] += a3 * kk.x; c[3][1] += a3 * kk.y; c[3][2] += a3 * kk.z; c[3][3] += a3 * kk.w;
    }

    float lo   = losq[0] * losq[0];
    float lg   = lgsq[0] * lgsq[0] + EPSf;
    float nf2  = nfp[0] * nfp[0] + EPSf;
    float tau2 = taup[0] * taup[0];

    int jb = j0 + tx * 4;
    float tj[4], nk[4];
#pragma unroll
    for (int q = 0; q < 4; q++) {
        tj[q] = g_t[jb + q];
        nk[q] = g_nk[b * 512 + jb + q];
    }

#pragma unroll
    for (int a = 0; a < 4; a++) {
        int i = i0 + ty * 4 + a;
        float ti = g_t[i];
        float nq = g_nq[b * 512 + i];
        float r[4];
#pragma unroll
        for (int q = 0; q < 4; q++) {
            float base = nf2 * (lo * fabsf(ti - tj[q]) + lg) + nq + nk[q] - 2.f * c[a][q];
            r[q] = (jb + q <= i) ? (-tau2 * logf(base)) : -INFINITY;
        }
        *(float4*)(g_s + ((size_t)(b * 512 + i) * 512 + jb)) = make_float4(r[0], r[1], r[2], r[3]);
    }
}

// ============================================================
// K2b: softmax rows + write A plane (+ zero imag)
// ============================================================
__global__ void __launch_bounds__(256) k_softmax(float* __restrict__ out)
{
    int row = blockIdx.x;
    int b = row >> 9, i = row & 511;
    int tid = threadIdx.x;

    __shared__ float red[256];
    float* srow = g_s + (size_t)row * 512;

    float v0 = (tid     <= i) ? srow[tid]       : -INFINITY;
    float v1 = (tid+256 <= i) ? srow[tid + 256] : -INFINITY;

    red[tid] = fmaxf(v0, v1);
    __syncthreads();
    for (int st = 128; st > 0; st >>= 1) {
        if (tid < st) red[tid] = fmaxf(red[tid], red[tid + st]);
        __syncthreads();
    }
    float mx = red[0];
    __syncthreads();

    float e0 = (tid     <= i) ? expf(v0 - mx) : 0.f;
    float e1 = (tid+256 <= i) ? expf(v1 - mx) : 0.f;
    red[tid] = e0 + e1;
    __syncthreads();
    for (int st = 128; st > 0; st >>= 1) {
        if (tid < st) red[tid] += red[tid + st];
        __syncthreads();
    }
    float inv = 1.f / red[0];

    float a0 = e0 * inv;
    float a1 = e1 * inv;
    srow[tid]       = a0;
    srow[tid + 256] = a1;
    size_t qoffr = QIJ_OFF + ((size_t)(b * 2 + 0) * 512 + i) * 512;
    size_t qoffi = QIJ_OFF + ((size_t)(b * 2 + 1) * 512 + i) * 512;
    out[qoffr + tid]       = a0;
    out[qoffr + tid + 256] = a1;
    out[qoffi + tid]       = 0.f;
    out[qoffi + tid + 256] = 0.f;
}

// ============================================================
// K2c: AV split-k GEMM. 64i x 128e tile, ONE 128-j chunk per block.
// grid 40 ; block 256 ; ~98KB smem. Partials to g_eP[ch].
// ============================================================
__global__ void __launch_bounds__(256) k_av()
{
    extern __shared__ float sm[];
    float* sA = sm;               // [64 i][132]  (128 j + pad)
    float* sV = sm + 64 * 132;    // [128 j][128 e]

    int bid = blockIdx.x;
    int b   = bid / 20;
    int t20 = bid % 20;
    int it  = AV_IT[t20];
    int ch  = AV_CH[t20];
    int i0  = it * 64;
    int jc  = ch * 128;

    int tid = threadIdx.x;
    int tx  = tid & 15;           // e group (8)
    int ty  = tid >> 4;           // i group (4)

    // stage A [i][j] for this chunk
    for (int idx4 = tid; idx4 < 64 * 32; idx4 += 256) {
        int r = idx4 >> 5, c = (idx4 & 31) * 4;
        float4 v = *(const float4*)(g_s + ((size_t)(b * 512 + i0 + r) * 512 + jc + c));
        float* p = sA + r * 132 + c;
        p[0] = v.x; p[1] = v.y; p[2] = v.z; p[3] = v.w;
    }
    // stage V [j][e]
    {
        const float4* src = (const float4*)(g_Uv + (size_t)(b * 512 + jc) * 128);
        for (int idx4 = tid; idx4 < 128 * 32; idx4 += 256)
            ((float4*)sV)[idx4] = src[idx4];
    }
    __syncthreads();

    float c0[8], c1[8], c2[8], c3[8];
#pragma unroll
    for (int q = 0; q < 8; q++) { c0[q]=0.f; c1[q]=0.f; c2[q]=0.f; c3[q]=0.f; }

#pragma unroll 4
    for (int j = 0; j < 128; j++) {
        float4 v0 = *(const float4*)(sV + j * 128 + tx * 8);
        float4 v1 = *(const float4*)(sV + j * 128 + tx * 8 + 4);
        float a0 = sA[(ty * 4 + 0) * 132 + j];
        float a1 = sA[(ty * 4 + 1) * 132 + j];
        float a2 = sA[(ty * 4 + 2) * 132 + j];
        float a3 = sA[(ty * 4 + 3) * 132 + j];
        float bv[8] = {v0.x, v0.y, v0.z, v0.w, v1.x, v1.y, v1.z, v1.w};
#pragma unroll
        for (int q = 0; q < 8; q++) {
            c0[q] += a0 * bv[q];
            c1[q] += a1 * bv[q];
            c2[q] += a2 * bv[q];
            c3[q] += a3 * bv[q];
        }
    }

    float* dstP = g_eP[ch];
#pragma unroll
    for (int a = 0; a < 4; a++) {
        float* cp = (a == 0) ? c0 : (a == 1) ? c1 : (a == 2) ? c2 : c3;
        float* dst = dstP + (size_t)(b * 512 + i0 + ty * 4 + a) * 128 + tx * 8;
        *(float4*)dst       = make_float4(cp[0], cp[1], cp[2], cp[3]);
        *(float4*)(dst + 4) = make_float4(cp[4], cp[5], cp[6], cp[7]);
    }
}

// ============================================================
// K2d: reduce split-k partials. grid 128 ; block 256 (float4)
// ============================================================
__global__ void __launch_bounds__(256) k_avred()
{
    int idx4 = blockIdx.x * 256 + threadIdx.x;     // 0..32767
    int row  = idx4 >> 5;                           // b*512 + i
    int i    = row & 511;
    int nch  = (i >> 7) + 1;

    float4 acc = ((const float4*)g_eP[0])[idx4];
    if (nch > 1) {
        float4 v = ((const float4*)g_eP[1])[idx4];
        acc.x += v.x; acc.y += v.y; acc.z += v.z; acc.w += v.w;
    }
    if (nch > 2) {
        float4 v = ((const float4*)g_eP[2])[idx4];
        acc.x += v.x; acc.y += v.y; acc.z += v.z; acc.w += v.w;
    }
    if (nch > 3) {
        float4 v = ((const float4*)g_eP[3])[idx4];
        acc.x += v.x; acc.y += v.y; acc.z += v.z; acc.w += v.w;
    }
    ((float4*)g_e)[idx4] = acc;
}

// ============================================================
// K3: estv / est_latent / P / output projection. grid 256 ; 4 rows/block
// ============================================================
__global__ void __launch_bounds__(256) k_epi(
    const float* __restrict__ Wp, const float* __restrict__ bp,
    const float* __restrict__ etap, float* __restrict__ out)
{
    int tid = threadIdx.x;
    int d   = tid & 63;
    int sub = tid >> 6;

    __shared__ float sW0[64 * 65];
    __shared__ float sW1[64 * 65];
    __shared__ float pbuf[4][2][64];

    {
        const float4* W04 = (const float4*)Wp;
        const float4* W14 = (const float4*)(Wp + 4096);
#pragma unroll
        for (int idx4 = tid; idx4 < 1024; idx4 += 256) {
            int r = idx4 >> 4, c = (idx4 & 15) * 4;
            float4 v0 = W04[idx4];
            float4 v1 = W14[idx4];
            float* p0 = sW0 + r * 65 + c;
            float* p1 = sW1 + r * 65 + c;
            p0[0] = v0.x; p0[1] = v0.y; p0[2] = v0.z; p0[3] = v0.w;
            p1[0] = v1.x; p1[1] = v1.y; p1[2] = v1.z; p1[3] = v1.w;
        }
    }
    float bR = bp[d], bI = bp[64 + d];
    float eta = 1.f / (1.f + expf(-etap[d]));
    float g   = 1.f / (1.f + expf(-eta));

    int row = blockIdx.x * 4 + sub;
    int b = row >> 9, i = row & 511;

    float efr = g_efr[i * 64 + d];
    float efi = g_efi[i * 64 + d];
    float er = g_e[row * 128 + d];
    float ei = g_e[row * 128 + 64 + d];
    float estr = efr * er - efi * ei;
    float esti = efr * ei + efi * er;

    float elr = (1.f - eta) * g_V[row * 128 + d]      + g * estr;
    float eli = (1.f - eta) * g_V[row * 128 + 64 + d] + g * esti;

    out[EST_OFF + ((size_t)(b * 2 + 0) * 512 + i) * 64 + d] = elr;
    out[EST_OFF + ((size_t)(b * 2 + 1) * 512 + i) * 64 + d] = eli;

    pbuf[sub][0][d] = efr * elr - efi * eli;
    pbuf[sub][1][d] = efr * eli + efi * elr;
    __syncthreads();

    float yr = bR, yi = bI;
#pragma unroll 16
    for (int e = 0; e < 64; e++) {
        float w0 = sW0[d * 65 + e];
        float w1 = sW1[d * 65 + e];
        float a = pbuf[sub][0][e];
        float c = pbuf[sub][1][e];
        yr += a * w0 - c * w1;
        yi += a * w1 + c * w0;
    }
    out[OUT_OFF + ((size_t)(b * 2 + 0) * 512 + i) * 64 + d] = yr;
    out[OUT_OFF + ((size_t)(b * 2 + 1) * 512 + i) * 64 + d] = yi;
}

// ============================================================
// K4: Z_ij_hat_all — 268 MB write. 4 i's per block; Uv staged in smem
// (cuts L2 read traffic 4x). grid 256 ; block 256.
// ============================================================
__global__ void __launch_bounds__(256) k_zij(float* __restrict__ out)
{
    __shared__ __align__(16) float sUv[64 * 128];   // 64 j rows x 128
    __shared__ __align__(16) float efr_s[4 * 64], efi_s[4 * 64];

    int blk = blockIdx.x;
    int b   = blk >> 7;
    int ig  = blk & 127;
    int i0  = ig * 4;
    int tid = threadIdx.x;

    {
        int il = tid >> 6, dd = tid & 63;
        efr_s[tid] = g_efr[(i0 + il) * 64 + dd];
        efi_s[tid] = g_efi[(i0 + il) * 64 + dd];
    }

    const float4* uv4 = (const float4*)(g_Uv + (size_t)b * 512 * 128);
    float4* sUv4 = (float4*)sUv;

    for (int jc = 0; jc < 512; jc += 64) {
        __syncthreads();
#pragma unroll
        for (int idx = tid; idx < 64 * 32; idx += 256)
            sUv4[idx] = uv4[(size_t)(jc + (idx >> 5)) * 32 + (idx & 31)];
        __syncthreads();

#pragma unroll
        for (int il = 0; il < 4; il++) {
            int i = i0 + il;
            float4* zr4 = (float4*)(out + Z_OFF + ((size_t)(b * 2 + 0) * 512 + i) * 32768);
            float4* zi4 = (float4*)(out + Z_OFF + ((size_t)(b * 2 + 1) * 512 + i) * 32768);
            const float* er = efr_s + il * 64;
            const float* ei = efi_s + il * 64;
#pragma unroll
            for (int k = tid; k < 64 * 16; k += 256) {
                int j  = k >> 4;
                int d4 = k & 15;
                int d  = d4 << 2;
                float4 vr = sUv4[j * 32 + d4];
                float4 vi = sUv4[j * 32 + 16 + d4];
                float e0 = er[d],     f0 = ei[d];
                float e1 = er[d + 1], f1 = ei[d + 1];
                float e2 = er[d + 2], f2 = ei[d + 2];
                float e3 = er[d + 3], f3 = ei[d + 3];
                float4 zr, zi;
                zr.x = e0 * vr.x - f0 * vi.x;  zi.x = e0 * vi.x + f0 * vr.x;
                zr.y = e1 * vr.y - f1 * vi.y;  zi.y = e1 * vi.y + f1 * vr.y;
                zr.z = e2 * vr.z - f2 * vi.z;  zi.z = e2 * vi.z + f2 * vr.z;
                zr.w = e3 * vr.w - f3 * vi.w;  zi.w = e3 * vi.w + f3 * vr.w;
                int o = (jc + j) * 16 + d4;
                __stcs(&zr4[o], zr);
                __stcs(&zi4[o], zi);
            }
        }
    }
}

// ============================================================
extern "C" void kernel_launch(void* const* d_in, const int* in_sizes, int n_in,
                              void* d_out, int out_size)
{
    const float* Zq   = (const float*)d_in[0];
    const float* Zk   = (const float*)d_in[1];
    const float* Zv   = (const float*)d_in[2];
    const float* tm   = (const float*)d_in[3];
    const float* Wq   = (const float*)d_in[4];
    const float* bq   = (const float*)d_in[5];
    const float* Wk   = (const float*)d_in[6];
    const float* bk   = (const float*)d_in[7];
    const float* Wv   = (const float*)d_in[8];
    const float* bv   = (const float*)d_in[9];
    const float* Wp   = (const float*)d_in[10];
    const float* bp   = (const float*)d_in[11];
    const float* lv   = (const float*)d_in[12];
    const float* losq = (const float*)d_in[13];
    const float* lgsq = (const float*)d_in[14];
    const float* nf   = (const float*)d_in[15];
    const float* tau  = (const float*)d_in[16];
    const float* etap = (const float*)d_in[17];
    float* out = (float*)d_out;

    static cudaStream_t s_z = nullptr;
    static cudaEvent_t ev_fork = nullptr, ev_join = nullptr;
    static const int sc_smem = (64 * 132 + 128 * 68) * 4;    // ~68.6KB
    static const int av_smem = (64 * 132 + 128 * 128) * 4;   // ~97.8KB
    if (s_z == nullptr) {
        cudaStreamCreateWithFlags(&s_z, cudaStreamNonBlocking);
        cudaEventCreateWithFlags(&ev_fork, cudaEventDisableTiming);
        cudaEventCreateWithFlags(&ev_join, cudaEventDisableTiming);
        cudaFuncSetAttribute(k_scores, cudaFuncAttributeMaxDynamicSharedMemorySize, sc_smem);
        cudaFuncSetAttribute(k_av,     cudaFuncAttributeMaxDynamicSharedMemorySize, av_smem);
    }

    k_setup<<<64, 512>>>(tm, lv, out + LH_OFF);
    k_proj<<<dim3(256, 3), 256>>>(Zq, Zk, Zv, Wq, bq, Wk, bk, Wv, bv);

    // fork: Z-plane writer overlaps with attention chain + epilogue
    cudaEventRecord(ev_fork, 0);
    cudaStreamWaitEvent(s_z, ev_fork, 0);
    k_zij<<<256, 256, 0, s_z>>>(out);
    cudaEventRecord(ev_join, s_z);

    k_scores<<<72, 256, sc_smem>>>(losq, lgsq, nf, tau);
    k_softmax<<<Bn * Nn, 256>>>(out);
    k_av<<<40, 256, av_smem>>>();
    k_avred<<<128, 256>>>();
    k_epi<<<256, 256>>>(Wp, bp, etap, out);

    cudaStreamWaitEvent(0, ev_join, 0);
}